// round 14
// baseline (speedup 1.0000x reference)
#include <cuda_runtime.h>
#include <cstdint>

// VQExpert fused kernel, round 14 = R13 + argmax-form packed-key scan:
//   dot' = z.c - cn/2 + B  (B=64, folded into f32x2 accumulator init)
//   argmax dot' == argmin score; positive-float keys compare as raw uints
//   (no fkey), complement-index in low byte for lowest-index tie-break.
//   Negative scores force the sign bit into the winning key -> detected ->
//   exact fallback, keeping the scheme sound without positivity proofs.

typedef unsigned long long ull;
#define FULLMASK 0xffffffffu

constexpr int NROW   = 500000;
constexpr int WARPS  = 16;
constexpr int RPW    = 8;
constexpr int TILE   = WARPS * RPW;              // 128
constexpr int NTILES = (NROW + TILE - 1) / TILE; // 3907
constexpr float BOFF = 64.0f;                    // positivity offset
constexpr float TH   = 1.2e-2f;                  // margin guard (dot units)

// smem layout (floats)
constexpr int O_WD2 = 0;          // 128x128 k-pair (exact path)
constexpr int O_M2  = 16384;      // 32x128 quad
constexpr int O_WP2 = 20480;      // 32x128 quad
constexpr int O_CB  = 24576;      // codebook quad
constexpr int O_CN  = 32768;      // 256 code norms
constexpr int O_BD  = 33024;
constexpr int O_BP  = 33152;
constexpr int O_BZ  = 33184;
constexpr int O_TS  = 33216;                      // 16 warps x (8 rows x 128)
constexpr int O_ZA  = O_TS + WARPS * RPW * 128;   // 16 warps x (8 x 32)
constexpr int O_HS  = O_ZA + WARPS * RPW * 32;    // 16 warps x 128 scratch h
constexpr int SMEM_FLOATS = O_HS + WARPS * 128;   // 55744
constexpr int SMEM_BYTES  = SMEM_FLOATS * 4;      // 222,976 B

__device__ float g_T[256 * 128];
__device__ float g_M[32 * 128];
__device__ float g_bz[32];

__device__ __forceinline__ ull ffma2(ull a, ull b, ull c) {
    ull d;
    asm("fma.rn.f32x2 %0, %1, %2, %3;" : "=l"(d) : "l"(a), "l"(b), "l"(c));
    return d;
}
__device__ __forceinline__ float f2sum(ull v) {
    float a, b;
    asm("mov.b64 {%0, %1}, %2;" : "=f"(a), "=f"(b) : "l"(v));
    return a + b;
}
__device__ __forceinline__ ull packf2(float lo, float hi) {
    ull r;
    asm("mov.b64 %0, {%1, %2};" : "=l"(r) : "f"(lo), "f"(hi));
    return r;
}
__device__ __forceinline__ void cpa16(uint32_t daddr, const void* g) {
    asm volatile("cp.async.ca.shared.global [%0], [%1], 16;" :: "r"(daddr), "l"(g));
}
__device__ __forceinline__ void cpa_commit() { asm volatile("cp.async.commit_group;"); }
__device__ __forceinline__ void cpa_wait0()  { asm volatile("cp.async.wait_group 0;"); }
__device__ __forceinline__ unsigned fkey(float s) {
    unsigned u = __float_as_uint(s);
    return u ^ ((u >> 31) ? 0xFFFFFFFFu : 0x80000000u);
}

// ---------------- prologue ----------------
__global__ void __launch_bounds__(128)
vq_precompute_kernel(const float* __restrict__ cb,
                     const float* __restrict__ Wd, const float* __restrict__ bd,
                     const float* __restrict__ Wp, const float* __restrict__ bp,
                     const float* __restrict__ Wo, const float* __restrict__ bo,
                     const float* __restrict__ Wu, const float* __restrict__ bu)
{
    __shared__ float v[128];
    const int i = threadIdx.x;
    const int c = blockIdx.x;
    if (c < 256) {
        float s = 0.f;
        #pragma unroll 8
        for (int d = 0; d < 32; d++) s = fmaf(cb[c * 32 + d], Wo[i * 32 + d], s);
        v[i] = s;
        __syncthreads();
        float t = 0.f, Bi = bu[i];
        #pragma unroll 8
        for (int j = 0; j < 128; j++) {
            t  = fmaf(v[j],  Wu[i * 128 + j], t);
            Bi = fmaf(bo[j], Wu[i * 128 + j], Bi);
        }
        g_T[c * 128 + i] = t + Bi;
    } else if (c < 288) {
        int zc = c - 256;
        double s = 0.0;
        for (int h = 0; h < 128; h++)
            s += (double)Wp[zc * 128 + h] * (double)Wd[h * 128 + i];
        g_M[zc * 128 + i] = (float)s;
    } else if (i < 32) {
        double s = (double)bp[i];
        for (int h = 0; h < 128; h++) s += (double)Wp[i * 128 + h] * (double)bd[h];
        g_bz[i] = (float)s;
    }
}

// exact two-step recompute for one row (bit-identical order to the R4 path).
__device__ __noinline__ int exact_row(const float* sm, const float* xrow,
                                      float* hs, float* zrow, int lane,
                                      float2 bd0, float2 bd1, float bpv)
{
    ull a0 = 0, a1 = 0, a2 = 0, a3 = 0;
    for (int pp = 0; pp < 32; pp++) {
        const float* b0 = sm + O_WD2 + (2 * pp) * 256;
        const float* b1 = b0 + 256;
        ulonglong2 wa0 = *(const ulonglong2*)(b0 + 4 * lane);
        ulonglong2 wb0 = *(const ulonglong2*)(b0 + 128 + 4 * lane);
        ulonglong2 wa1 = *(const ulonglong2*)(b1 + 4 * lane);
        ulonglong2 wb1 = *(const ulonglong2*)(b1 + 128 + 4 * lane);
        ulonglong2 xv  = *(const ulonglong2*)(xrow + 4 * pp);
        a0 = ffma2(xv.x, wa0.x, a0); a1 = ffma2(xv.x, wa0.y, a1);
        a2 = ffma2(xv.x, wb0.x, a2); a3 = ffma2(xv.x, wb0.y, a3);
        a0 = ffma2(xv.y, wa1.x, a0); a1 = ffma2(xv.y, wa1.y, a1);
        a2 = ffma2(xv.y, wb1.x, a2); a3 = ffma2(xv.y, wb1.y, a3);
    }
    __syncwarp();
    hs[2 * lane]          = bd0.x + f2sum(a0);
    hs[2 * lane + 1]      = bd0.y + f2sum(a1);
    hs[64 + 2 * lane]     = bd1.x + f2sum(a2);
    hs[64 + 2 * lane + 1] = bd1.y + f2sum(a3);
    __syncwarp();
    ull zacc = 0;
    for (int kq = 0; kq < 32; kq++) {
        ulonglong2 w  = *(const ulonglong2*)(sm + O_WP2 + kq * 128 + 4 * lane);
        ulonglong2 h2 = *(const ulonglong2*)(hs + 4 * kq);
        zacc = ffma2(h2.x, w.x, zacc);
        zacc = ffma2(h2.y, w.y, zacc);
    }
    __syncwarp();
    zrow[lane] = bpv + f2sum(zacc);
    __syncwarp();
    ull dd[8];
    #pragma unroll
    for (int g = 0; g < 8; g++) dd[g] = 0ull;
    for (int dq = 0; dq < 8; dq++) {
        ulonglong2 zq = *(const ulonglong2*)(zrow + 4 * dq);
        #pragma unroll
        for (int g = 0; g < 8; g++) {
            ulonglong2 c2 = *(const ulonglong2*)(sm + O_CB + dq * 1024 + (g * 32 + lane) * 4);
            dd[g] = ffma2(zq.x, c2.x, dd[g]);
            dd[g] = ffma2(zq.y, c2.y, dd[g]);
        }
    }
    unsigned bk = 0xFFFFFFFFu, bi = 0;
    #pragma unroll
    for (int g = 0; g < 8; g++) {
        float s = sm[O_CN + g * 32 + lane] - 2.0f * f2sum(dd[g]);
        unsigned k = fkey(s);
        if (k < bk) { bk = k; bi = (unsigned)((g << 5) | lane); }
    }
    unsigned m = __reduce_min_sync(FULLMASK, bk);
    unsigned cand = (bk == m) ? bi : 0xFFFFFFFFu;
    return (int)__reduce_min_sync(FULLMASK, cand);
}

// ---------------- main kernel ----------------
__global__ void __launch_bounds__(512, 1)
vq_expert_kernel(const float* __restrict__ x,
                 const float* __restrict__ Wd, const float* __restrict__ bd,
                 const float* __restrict__ Wp, const float* __restrict__ bp,
                 const float* __restrict__ cb,
                 float* __restrict__ out)
{
    extern __shared__ float sm[];
    const int tid = threadIdx.x;

    for (int i = tid; i < 128 * 128; i += 512) {
        int j = i >> 7, k = i & 127;
        sm[O_WD2 + (k >> 1) * 256 + j * 2 + (k & 1)] = Wd[i];
    }
    for (int i = tid; i < 4096; i += 512) {
        int c = i >> 7, k = i & 127;
        sm[O_M2  + (k >> 2) * 128 + c * 4 + (k & 3)] = g_M[i];
        sm[O_WP2 + (k >> 2) * 128 + c * 4 + (k & 3)] = Wp[i];
    }
    for (int i = tid; i < 256 * 32; i += 512) {
        int c = i >> 5, d = i & 31;
        sm[O_CB + (d >> 2) * 1024 + c * 4 + (d & 3)] = cb[i];
    }
    for (int c = tid; c < 256; c += 512) {
        float s = 0.f;
        #pragma unroll 8
        for (int d = 0; d < 32; d++) { float v = cb[c * 32 + d]; s = fmaf(v, v, s); }
        sm[O_CN + c] = s;
    }
    if (tid < 128) sm[O_BD + tid] = bd[tid];
    else if (tid < 160) sm[O_BP + tid - 128] = bp[tid - 128];
    else if (tid < 192) sm[O_BZ + tid - 160] = g_bz[tid - 160];
    if (blockIdx.x == 0 && tid == 0)
        out[(size_t)NROW * 128 + NROW] = 0.0f;    // commit_loss == 0 exactly
    __syncthreads();

    const int wid  = tid >> 5;
    const int lane = tid & 31;
    float* myts = sm + O_TS + wid * (RPW * 128);
    float* myza = sm + O_ZA + wid * (RPW * 32);
    float* myhs = sm + O_HS + wid * 128;

    const float2 bd0 = *(const float2*)(sm + O_BD + 2 * lane);
    const float2 bd1 = *(const float2*)(sm + O_BD + 64 + 2 * lane);
    const float  bpv = sm[O_BP + lane];
    const float  bzv = sm[O_BZ + lane];
    float cnB[8];                         // B - cn/2, folded into accumulator init
    #pragma unroll
    for (int g = 0; g < 8; g++) cnB[g] = BOFF - 0.5f * sm[O_CN + g * 32 + lane];

    float* outY = out;
    float* outI = out + (size_t)NROW * 128;

    uint32_t sb = (uint32_t)__cvta_generic_to_shared(myts + 4 * lane);

    for (int tile = blockIdx.x; tile < NTILES; tile += gridDim.x) {
        const int row0 = tile * TILE + wid * RPW;
        if (row0 >= NROW) continue;
        const bool full = (row0 + RPW <= NROW);

        // stage x (stays live through the whole tile for the exact fallback)
        #pragma unroll
        for (int r = 0; r < RPW; r++)
            if (full || row0 + r < NROW)
                cpa16(sb + r * 512, x + (size_t)(row0 + r) * 128 + 4 * lane);
        cpa_commit();
        cpa_wait0();
        __syncwarp();

        // -------- folded z: z_f = x @ M^T + bz, lane = z-column --------
        ull za[RPW];
        #pragma unroll
        for (int r = 0; r < RPW; r++) za[r] = 0ull;
        #pragma unroll 4
        for (int kq = 0; kq < 32; kq++) {
            ulonglong2 w = *(const ulonglong2*)(sm + O_M2 + kq * 128 + 4 * lane);
            #pragma unroll
            for (int r = 0; r < RPW; r++) {
                ulonglong2 xk = *(const ulonglong2*)(myts + r * 128 + 4 * kq);
                za[r] = ffma2(xk.x, w.x, za[r]);
                za[r] = ffma2(xk.y, w.y, za[r]);
            }
        }
        __syncwarp();
        #pragma unroll
        for (int r = 0; r < RPW; r++)
            myza[r * 32 + lane] = bzv + f2sum(za[r]);
        __syncwarp();

        // -------- argmax scan: dot' = z.c - cn/2 + B, packed uint keys --------
        unsigned bk[RPW], sk[RPW];
        #pragma unroll
        for (int r = 0; r < RPW; r++) { bk[r] = 0u; sk[r] = 0u; }

        #pragma unroll
        for (int half = 0; half < 2; half++) {
            ull da[RPW][4];
            #pragma unroll
            for (int r = 0; r < RPW; r++)
                #pragma unroll
                for (int i = 0; i < 4; i++)
                    da[r][i] = packf2(cnB[half * 4 + i], 0.0f);

            #pragma unroll 2
            for (int dq = 0; dq < 8; dq++) {
                ulonglong2 c2[4];
                #pragma unroll
                for (int i = 0; i < 4; i++)
                    c2[i] = *(const ulonglong2*)(sm + O_CB + dq * 1024
                                + ((half * 4 + i) * 32 + lane) * 4);
                #pragma unroll
                for (int r = 0; r < RPW; r++) {
                    ulonglong2 zq = *(const ulonglong2*)(myza + r * 32 + 4 * dq);
                    #pragma unroll
                    for (int i = 0; i < 4; i++) {
                        da[r][i] = ffma2(zq.x, c2[i].x, da[r][i]);
                        da[r][i] = ffma2(zq.y, c2[i].y, da[r][i]);
                    }
                }
            }
            #pragma unroll
            for (int r = 0; r < RPW; r++) {
                #pragma unroll
                for (int i = 0; i < 4; i++) {
                    int g = half * 4 + i;
                    float s = f2sum(da[r][i]);           // dot' (positive normally)
                    unsigned pk = (__float_as_uint(s) & 0xFFFFFF00u)
                                | ((unsigned)((g << 5) | lane) ^ 0xFFu);
                    unsigned nb = umax(bk[r], pk);
                    sk[r] = umax(sk[r], umin(bk[r], pk));
                    bk[r] = nb;
                }
            }
        }

        int bc[RPW];
        #pragma unroll
        for (int r = 0; r < RPW; r++) {
            unsigned m1 = __reduce_max_sync(FULLMASK, bk[r]);
            unsigned cand = (bk[r] == m1) ? sk[r] : bk[r];
            unsigned m2 = __reduce_max_sync(FULLMASK, cand);
            int idx = (int)((m1 & 0xFFu) ^ 0xFFu);
            float margin = __uint_as_float(m1 & 0xFFFFFF00u)
                         - __uint_as_float(m2 & 0xFFFFFF00u);
            // fallback if margin small OR any score went negative (sign bit in m1)
            if ((((int)m1 < 0) || !(margin >= TH)) && (full || row0 + r < NROW)) {
                idx = exact_row(sm, myts + r * 128, myhs, myza + r * 32,
                                lane, bd0, bd1, bpv);
            }
            bc[r] = idx;
        }

        // -------- epilogue: y = clamp(T[bc], -1, 1) --------
        #pragma unroll
        for (int r = 0; r < RPW; r++) {
            if (full || row0 + r < NROW) {
                float4 t = ((const float4*)(g_T + bc[r] * 128))[lane];
                float4 y;
                y.x = fminf(fmaxf(t.x, -1.0f), 1.0f);
                y.y = fminf(fmaxf(t.y, -1.0f), 1.0f);
                y.z = fminf(fmaxf(t.z, -1.0f), 1.0f);
                y.w = fminf(fmaxf(t.w, -1.0f), 1.0f);
                ((float4*)(outY + (size_t)(row0 + r) * 128))[lane] = y;
            }
        }
        if (lane == 0) {
            #pragma unroll
            for (int r = 0; r < RPW; r++)
                if (row0 + r < NROW) outI[row0 + r] = (float)bc[r];
        }
        __syncwarp();
    }
}

extern "C" void kernel_launch(void* const* d_in, const int* in_sizes, int n_in,
                              void* d_out, int out_size)
{
    const float* x  = (const float*)d_in[0];
    const float* Wd = (const float*)d_in[1];
    const float* bd = (const float*)d_in[2];
    const float* Wp = (const float*)d_in[3];
    const float* bp = (const float*)d_in[4];
    const float* cb = (const float*)d_in[5];
    const float* Wo = (const float*)d_in[6];
    const float* bo = (const float*)d_in[7];
    const float* Wu = (const float*)d_in[8];
    const float* bu = (const float*)d_in[9];
    float* out = (float*)d_out;

    cudaFuncSetAttribute(vq_expert_kernel,
                         cudaFuncAttributeMaxDynamicSharedMemorySize, SMEM_BYTES);

    vq_precompute_kernel<<<289, 128>>>(cb, Wd, bd, Wp, bp, Wo, bo, Wu, bu);
    vq_expert_kernel<<<148, 512, SMEM_BYTES>>>(x, Wd, bd, Wp, bp, cb, out);
}

// round 16
// speedup vs baseline: 1.2148x; 1.2148x over previous
#include <cuda_runtime.h>
#include <cuda_bf16.h>
#include <cstdint>

// VQExpert round 16: legacy mma.sync (bf16 HMMA, PTX-portable) for the argmin
// GEMM + fp32 f32x2 z-fold + margin-guarded exact fallback (weights from global).
//   fold:  z = x @ M^T + bz        (fp32 f32x2, R13-validated)
//   score: S(16x256) = [zh zl zh](16x96) @ [ch ch cl]^T  via mma.sync.m16n8k16
//   scan:  argmax dot' = z.c + 64 - cn/2, packed uint keys (R14-validated)
//   guard: margin < TH or sign bit -> exact_row (R4 bit-exact, global weights)
//   y = clamp(T[idx])

typedef unsigned long long ull;
#define FULLMASK 0xffffffffu

constexpr int NROW   = 500000;
constexpr int WARPS  = 14;
constexpr int THREADS = WARPS * 32;              // 448
constexpr int RPW    = 16;                       // rows per warp (mma M=16)
constexpr int TILE   = WARPS * RPW;              // 224
constexpr int NTILES = (NROW + TILE - 1) / TILE; // 2233
constexpr float BOFF = 64.0f;
constexpr float TH   = 1.2e-2f;

// smem layout (float units)
constexpr int O_M2  = 0;        // 32x128 quad (fold)
constexpr int O_CNB = 4096;     // 256: 64 - cn/2
constexpr int O_CN  = 4352;     // 256 code norms (exact path)
constexpr int O_BD  = 4608;
constexpr int O_BP  = 4736;
constexpr int O_BZ  = 4768;
constexpr int O_B2F = 4800;     // cb fragments: 4kt x 32nt x 32lane x uint2 = 8192 floats
constexpr int O_TS  = 12992;    // 14 warps x (16 rows x 128) x fp32
constexpr int O_ZS  = O_TS + WARPS * RPW * 128;       // 14 x (16 x 34) z staged
constexpr int O_HS  = O_ZS + WARPS * RPW * 34;        // 14 x 160 exact scratch
constexpr int O_BC  = O_HS + WARPS * 160;             // 14 x 16 idx
constexpr int SMEM_FLOATS = O_BC + WARPS * 16;        // 51744
constexpr int SMEM_BYTES  = SMEM_FLOATS * 4;          // 206,976 B

__device__ float g_T[256 * 128];
__device__ float g_M[32 * 128];
__device__ float g_bz[32];
__device__ __align__(16) float g_Wd2[128 * 128];  // k-pair interleave (exact path)
__device__ __align__(16) float g_Wp2[32 * 128];   // quad (exact path)
__device__ __align__(16) float g_cbq[256 * 32];   // quad (exact path)
__device__ unsigned g_B2f[8192];                  // cb mma B-fragments (bf16x2)

__device__ __forceinline__ ull ffma2(ull a, ull b, ull c) {
    ull d;
    asm("fma.rn.f32x2 %0, %1, %2, %3;" : "=l"(d) : "l"(a), "l"(b), "l"(c));
    return d;
}
__device__ __forceinline__ float f2sum(ull v) {
    float a, b;
    asm("mov.b64 {%0, %1}, %2;" : "=f"(a), "=f"(b) : "l"(v));
    return a + b;
}
__device__ __forceinline__ void cpa16(uint32_t daddr, const void* g) {
    asm volatile("cp.async.ca.shared.global [%0], [%1], 16;" :: "r"(daddr), "l"(g));
}
__device__ __forceinline__ void cpa_commit() { asm volatile("cp.async.commit_group;"); }
__device__ __forceinline__ void cpa_wait0()  { asm volatile("cp.async.wait_group 0;"); }
__device__ __forceinline__ unsigned fkey(float s) {
    unsigned u = __float_as_uint(s);
    return u ^ ((u >> 31) ? 0xFFFFFFFFu : 0x80000000u);
}
// pack bf16x2: lo = a, hi = b
__device__ __forceinline__ unsigned cvt_bf16x2(float a, float b) {
    unsigned r;
    asm("cvt.rn.bf16x2.f32 %0, %1, %2;" : "=r"(r) : "f"(b), "f"(a));
    return r;
}
__device__ __forceinline__ unsigned bf16bits(float f) {
    __nv_bfloat16 h = __float2bfloat16(f);
    return (unsigned)*(unsigned short*)&h;
}
__device__ __forceinline__ void mma_bf16(float* c, const unsigned* a, unsigned b0, unsigned b1) {
    asm volatile("mma.sync.aligned.m16n8k16.row.col.f32.bf16.bf16.f32 "
                 "{%0,%1,%2,%3}, {%4,%5,%6,%7}, {%8,%9}, {%0,%1,%2,%3};"
                 : "+f"(c[0]), "+f"(c[1]), "+f"(c[2]), "+f"(c[3])
                 : "r"(a[0]), "r"(a[1]), "r"(a[2]), "r"(a[3]), "r"(b0), "r"(b1));
}

// ---------------- prologue ----------------
__global__ void __launch_bounds__(128)
vq_precompute_kernel(const float* __restrict__ cb,
                     const float* __restrict__ Wd, const float* __restrict__ bd,
                     const float* __restrict__ Wp, const float* __restrict__ bp,
                     const float* __restrict__ Wo, const float* __restrict__ bo,
                     const float* __restrict__ Wu, const float* __restrict__ bu)
{
    __shared__ float v[128];
    const int i = threadIdx.x;
    const int c = blockIdx.x;
    if (c < 256) {
        float s = 0.f;
        #pragma unroll 8
        for (int d = 0; d < 32; d++) s = fmaf(cb[c * 32 + d], Wo[i * 32 + d], s);
        v[i] = s;
        __syncthreads();
        float t = 0.f, Bi = bu[i];
        #pragma unroll 8
        for (int j = 0; j < 128; j++) {
            t  = fmaf(v[j],  Wu[i * 128 + j], t);
            Bi = fmaf(bo[j], Wu[i * 128 + j], Bi);
        }
        g_T[c * 128 + i] = t + Bi;

        const int t0 = c * 128 + i;              // 0..32767
        if (t0 < 16384) {                        // pack Wd -> k-pair interleave
            int j = t0 >> 7, k = t0 & 127;
            g_Wd2[(k >> 1) * 256 + j * 2 + (k & 1)] = Wd[t0];
        }
        if (t0 < 4096) {                         // pack Wp -> quad
            int cc = t0 >> 7, k = t0 & 127;
            g_Wp2[(k >> 2) * 128 + cc * 4 + (k & 3)] = Wp[t0];
        }
        if (t0 < 8192) {                         // pack cb -> quad (exact path)
            int cc = t0 >> 5, d = t0 & 31;
            g_cbq[(d >> 2) * 1024 + cc * 4 + (d & 3)] = cb[t0];
        }
        if (t0 < 8192) {                         // cb mma B-fragments
            unsigned u = (unsigned)t0;
            int kt = u >> 11, rem = u & 2047;
            int nt = rem >> 6, rem2 = rem & 63;
            int l = rem2 >> 1, r = rem2 & 1;
            int n = nt * 8 + (l >> 2);
            int kin = 2 * (l & 3) + r * 8;
            int d = (kt & 1) * 16 + kin;         // dim 0..30 (pairs)
            float f0 = cb[n * 32 + d], f1 = cb[n * 32 + d + 1];
            unsigned v0, v1;
            if (kt < 2) { v0 = bf16bits(f0); v1 = bf16bits(f1); }
            else {
                float h0 = __bfloat162float(__float2bfloat16(f0));
                float h1 = __bfloat162float(__float2bfloat16(f1));
                v0 = bf16bits(f0 - h0); v1 = bf16bits(f1 - h1);
            }
            g_B2f[u] = v0 | (v1 << 16);
        }
    } else if (c < 288) {
        int zc = c - 256;
        double s = 0.0;
        for (int h = 0; h < 128; h++)
            s += (double)Wp[zc * 128 + h] * (double)Wd[h * 128 + i];
        g_M[zc * 128 + i] = (float)s;
    } else if (i < 32) {
        double s = (double)bp[i];
        for (int h = 0; h < 128; h++) s += (double)Wp[i * 128 + h] * (double)bd[h];
        g_bz[i] = (float)s;
    }
}

// exact two-step recompute (R4 bit-exact order); weights from GLOBAL packed copies.
__device__ __noinline__ int exact_row_g(const float* __restrict__ xrow,
                                        const float* __restrict__ cnsm,
                                        float* hs, float* zrow, int lane,
                                        float2 bd0, float2 bd1, float bpv)
{
    ull a0 = 0, a1 = 0, a2 = 0, a3 = 0;
    for (int pp = 0; pp < 32; pp++) {
        const float* b0 = g_Wd2 + (2 * pp) * 256;
        const float* b1 = b0 + 256;
        ulonglong2 wa0 = *(const ulonglong2*)(b0 + 4 * lane);
        ulonglong2 wb0 = *(const ulonglong2*)(b0 + 128 + 4 * lane);
        ulonglong2 wa1 = *(const ulonglong2*)(b1 + 4 * lane);
        ulonglong2 wb1 = *(const ulonglong2*)(b1 + 128 + 4 * lane);
        ulonglong2 xv  = *(const ulonglong2*)(xrow + 4 * pp);
        a0 = ffma2(xv.x, wa0.x, a0); a1 = ffma2(xv.x, wa0.y, a1);
        a2 = ffma2(xv.x, wb0.x, a2); a3 = ffma2(xv.x, wb0.y, a3);
        a0 = ffma2(xv.y, wa1.x, a0); a1 = ffma2(xv.y, wa1.y, a1);
        a2 = ffma2(xv.y, wb1.x, a2); a3 = ffma2(xv.y, wb1.y, a3);
    }
    __syncwarp();
    hs[2 * lane]          = bd0.x + f2sum(a0);
    hs[2 * lane + 1]      = bd0.y + f2sum(a1);
    hs[64 + 2 * lane]     = bd1.x + f2sum(a2);
    hs[64 + 2 * lane + 1] = bd1.y + f2sum(a3);
    __syncwarp();
    ull zacc = 0;
    for (int kq = 0; kq < 32; kq++) {
        ulonglong2 w  = *(const ulonglong2*)(g_Wp2 + kq * 128 + 4 * lane);
        ulonglong2 h2 = *(const ulonglong2*)(hs + 4 * kq);
        zacc = ffma2(h2.x, w.x, zacc);
        zacc = ffma2(h2.y, w.y, zacc);
    }
    __syncwarp();
    zrow[lane] = bpv + f2sum(zacc);
    __syncwarp();
    ull dd[8];
    #pragma unroll
    for (int g = 0; g < 8; g++) dd[g] = 0ull;
    for (int dq = 0; dq < 8; dq++) {
        ulonglong2 zq = *(const ulonglong2*)(zrow + 4 * dq);
        #pragma unroll
        for (int g = 0; g < 8; g++) {
            ulonglong2 c2 = *(const ulonglong2*)(g_cbq + dq * 1024 + (g * 32 + lane) * 4);
            dd[g] = ffma2(zq.x, c2.x, dd[g]);
            dd[g] = ffma2(zq.y, c2.y, dd[g]);
        }
    }
    unsigned bk = 0xFFFFFFFFu, bi = 0;
    #pragma unroll
    for (int g = 0; g < 8; g++) {
        float s = cnsm[g * 32 + lane] - 2.0f * f2sum(dd[g]);
        unsigned k = fkey(s);
        if (k < bk) { bk = k; bi = (unsigned)((g << 5) | lane); }
    }
    unsigned m = __reduce_min_sync(FULLMASK, bk);
    unsigned cand = (bk == m) ? bi : 0xFFFFFFFFu;
    return (int)__reduce_min_sync(FULLMASK, cand);
}

// ---------------- main kernel ----------------
__global__ void __launch_bounds__(THREADS, 1)
vq_expert_kernel(const float* __restrict__ x,
                 const float* __restrict__ cb,
                 const float* __restrict__ bd, const float* __restrict__ bp,
                 float* __restrict__ out)
{
    extern __shared__ float sm[];
    const int tid  = threadIdx.x;
    const int wid  = tid >> 5;
    const int lane = tid & 31;

    // ---- stage static smem ----
    for (int i = tid; i < 4096; i += THREADS) {
        int c = i >> 7, k = i & 127;
        sm[O_M2 + (k >> 2) * 128 + c * 4 + (k & 3)] = g_M[i];
    }
    for (int i = tid; i < 8192; i += THREADS)
        ((unsigned*)(sm + O_B2F))[i] = g_B2f[i];
    for (int c = tid; c < 256; c += THREADS) {
        float s = 0.f;
        #pragma unroll 8
        for (int d = 0; d < 32; d++) { float v = cb[c * 32 + d]; s = fmaf(v, v, s); }
        sm[O_CN + c]  = s;
        sm[O_CNB + c] = BOFF - 0.5f * s;
    }
    if (tid < 128) sm[O_BD + tid] = bd[tid];
    else if (tid < 160) sm[O_BP + tid - 128] = bp[tid - 128];
    else if (tid < 192) sm[O_BZ + tid - 160] = g_bz[tid - 160];
    if (blockIdx.x == 0 && tid == 0)
        out[(size_t)NROW * 128 + NROW] = 0.0f;    // commit_loss == 0 exactly
    __syncthreads();

    float* myts = sm + O_TS + wid * (RPW * 128);
    float* myzs = sm + O_ZS + wid * (RPW * 34);
    float* myhs = sm + O_HS + wid * 160;
    float* myzr = myhs + 128;
    int*   bcw  = (int*)(sm + O_BC) + wid * 16;

    const float2 bd0 = *(const float2*)(sm + O_BD + 2 * lane);
    const float2 bd1 = *(const float2*)(sm + O_BD + 64 + 2 * lane);
    const float  bpv = sm[O_BP + lane];
    const float  bzv = sm[O_BZ + lane];

    const int g  = lane >> 2;
    const int tg = lane & 3;

    float* outY = out;
    float* outI = out + (size_t)NROW * 128;
    uint32_t sb = (uint32_t)__cvta_generic_to_shared(myts + 4 * lane);

    for (int tile = blockIdx.x; tile < NTILES; tile += gridDim.x) {
        const int row0 = tile * TILE + wid * RPW;
        if (row0 >= NROW) continue;

        // ---- stage x (16 rows, cp.async) ----
        #pragma unroll
        for (int r = 0; r < RPW; r++)
            if (row0 + r < NROW)
                cpa16(sb + r * 512, x + (size_t)(row0 + r) * 128 + 4 * lane);
        cpa_commit();
        cpa_wait0();
        __syncwarp();

        // ---- fold: z = x @ M^T + bz (fp32 f32x2, lane = z-col) ----
        {
            ull za[RPW];
            #pragma unroll
            for (int r = 0; r < RPW; r++) za[r] = 0ull;
            #pragma unroll 2
            for (int kq = 0; kq < 32; kq++) {
                ulonglong2 w = *(const ulonglong2*)(sm + O_M2 + kq * 128 + 4 * lane);
                #pragma unroll
                for (int r = 0; r < RPW; r++) {
                    ulonglong2 xk = *(const ulonglong2*)(myts + r * 128 + 4 * kq);
                    za[r] = ffma2(xk.x, w.x, za[r]);
                    za[r] = ffma2(xk.y, w.y, za[r]);
                }
            }
            __syncwarp();
            #pragma unroll
            for (int r = 0; r < RPW; r++)
                myzs[r * 34 + lane] = bzv + f2sum(za[r]);
            __syncwarp();
        }

        // ---- build A fragments: zh (kt0,1) and zl (kt2,3) ----
        unsigned A6[4][4];   // [0]=zh kt0, [1]=zh kt1, [2]=zl kt0, [3]=zl kt1
        #pragma unroll
        for (int kt = 0; kt < 2; kt++) {
            int c0 = kt * 16 + 2 * tg;
            float2 p00 = *(const float2*)(myzs + g * 34 + c0);
            float2 p10 = *(const float2*)(myzs + (g + 8) * 34 + c0);
            float2 p01 = *(const float2*)(myzs + g * 34 + c0 + 8);
            float2 p11 = *(const float2*)(myzs + (g + 8) * 34 + c0 + 8);
            A6[kt][0] = cvt_bf16x2(p00.x, p00.y);
            A6[kt][1] = cvt_bf16x2(p10.x, p10.y);
            A6[kt][2] = cvt_bf16x2(p01.x, p01.y);
            A6[kt][3] = cvt_bf16x2(p11.x, p11.y);
            // residuals
            float r00x = p00.x - __bfloat162float(__float2bfloat16(p00.x));
            float r00y = p00.y - __bfloat162float(__float2bfloat16(p00.y));
            float r10x = p10.x - __bfloat162float(__float2bfloat16(p10.x));
            float r10y = p10.y - __bfloat162float(__float2bfloat16(p10.y));
            float r01x = p01.x - __bfloat162float(__float2bfloat16(p01.x));
            float r01y = p01.y - __bfloat162float(__float2bfloat16(p01.y));
            float r11x = p11.x - __bfloat162float(__float2bfloat16(p11.x));
            float r11y = p11.y - __bfloat162float(__float2bfloat16(p11.y));
            A6[2 + kt][0] = cvt_bf16x2(r00x, r00y);
            A6[2 + kt][1] = cvt_bf16x2(r10x, r10y);
            A6[2 + kt][2] = cvt_bf16x2(r01x, r01y);
            A6[2 + kt][3] = cvt_bf16x2(r11x, r11y);
        }

        // ---- MMA scan: 32 ntiles (pairs), 6 K-steps each ----
        unsigned Bg = 0u, Sg = 0u, Bh = 0u, Sh = 0u;
        const uint2* Bf = (const uint2*)(sm + O_B2F);
        const int AI[6]  = {0, 1, 2, 3, 0, 1};   // A frag per step
        const int KB[6]  = {0, 1, 0, 1, 2, 3};   // B kt per step

        #pragma unroll 2
        for (int ntp = 0; ntp < 16; ntp++) {
            int nt0 = 2 * ntp, nt1 = nt0 + 1;
            float C0[4] = {0.f, 0.f, 0.f, 0.f};
            float C1[4] = {0.f, 0.f, 0.f, 0.f};
            #pragma unroll
            for (int s = 0; s < 6; s++) {
                uint2 b0 = Bf[(KB[s] * 32 + nt0) * 32 + lane];
                mma_bf16(C0, A6[AI[s]], b0.x, b0.y);
                uint2 b1 = Bf[(KB[s] * 32 + nt1) * 32 + lane];
                mma_bf16(C1, A6[AI[s]], b1.x, b1.y);
            }
            #pragma unroll
            for (int q = 0; q < 2; q++) {
                const float* C = q ? C1 : C0;
                int nt = q ? nt1 : nt0;
                float2 cnb = *(const float2*)(sm + O_CNB + nt * 8 + 2 * tg);
                int col0 = nt * 8 + 2 * tg;
                float sc; unsigned pk, nb;
                sc = C[0] + cnb.x;
                pk = (__float_as_uint(sc) & 0xFFFFFF00u) | ((unsigned)col0 ^ 0xFFu);
                nb = umax(Bg, pk); Sg = umax(Sg, umin(Bg, pk)); Bg = nb;
                sc = C[1] + cnb.y;
                pk = (__float_as_uint(sc) & 0xFFFFFF00u) | ((unsigned)(col0 + 1) ^ 0xFFu);
                nb = umax(Bg, pk); Sg = umax(Sg, umin(Bg, pk)); Bg = nb;
                sc = C[2] + cnb.x;
                pk = (__float_as_uint(sc) & 0xFFFFFF00u) | ((unsigned)col0 ^ 0xFFu);
                nb = umax(Bh, pk); Sh = umax(Sh, umin(Bh, pk)); Bh = nb;
                sc = C[3] + cnb.y;
                pk = (__float_as_uint(sc) & 0xFFFFFF00u) | ((unsigned)(col0 + 1) ^ 0xFFu);
                nb = umax(Bh, pk); Sh = umax(Sh, umin(Bh, pk)); Bh = nb;
            }
        }

        // ---- quad reduce (4 lanes per row) ----
        #pragma unroll
        for (int off = 1; off <= 2; off <<= 1) {
            unsigned ob = __shfl_xor_sync(FULLMASK, Bg, off);
            unsigned os = __shfl_xor_sync(FULLMASK, Sg, off);
            Sg = umax(umax(Sg, os), umin(Bg, ob)); Bg = umax(Bg, ob);
            ob = __shfl_xor_sync(FULLMASK, Bh, off);
            os = __shfl_xor_sync(FULLMASK, Sh, off);
            Sh = umax(umax(Sh, os), umin(Bh, ob)); Bh = umax(Bh, ob);
        }
        if (tg == 0) {
            unsigned Bs[2] = {Bg, Bh}, Ss[2] = {Sg, Sh};
            #pragma unroll
            for (int h = 0; h < 2; h++) {
                int r = g + h * 8;
                int res = 0;
                if (row0 + r < NROW) {
                    unsigned B = Bs[h], S = Ss[h];
                    float margin = __uint_as_float(B & 0xFFFFFF00u)
                                 - __uint_as_float(S & 0xFFFFFF00u);
                    res = (((int)B < 0) || !(margin >= TH))
                        ? -1 : (int)((B & 0xFFu) ^ 0xFFu);
                }
                bcw[r] = res;
            }
        }
        __syncwarp();

        // ---- fallback + epilogue ----
        #pragma unroll 4
        for (int r = 0; r < RPW; r++) {
            int grow = row0 + r;
            if (grow >= NROW) continue;
            int idx = bcw[r];
            if (idx < 0)
                idx = exact_row_g(x + (size_t)grow * 128, sm + O_CN,
                                  myhs, myzr, lane, bd0, bd1, bpv);
            float4 t = ((const float4*)(g_T + idx * 128))[lane];
            float4 y;
            y.x = fminf(fmaxf(t.x, -1.0f), 1.0f);
            y.y = fminf(fmaxf(t.y, -1.0f), 1.0f);
            y.z = fminf(fmaxf(t.z, -1.0f), 1.0f);
            y.w = fminf(fmaxf(t.w, -1.0f), 1.0f);
            ((float4*)(outY + (size_t)grow * 128))[lane] = y;
            if (lane == 0) outI[grow] = (float)idx;
        }
        __syncwarp();
    }
}

extern "C" void kernel_launch(void* const* d_in, const int* in_sizes, int n_in,
                              void* d_out, int out_size)
{
    const float* x  = (const float*)d_in[0];
    const float* Wd = (const float*)d_in[1];
    const float* bd = (const float*)d_in[2];
    const float* Wp = (const float*)d_in[3];
    const float* bp = (const float*)d_in[4];
    const float* cb = (const float*)d_in[5];
    const float* Wo = (const float*)d_in[6];
    const float* bo = (const float*)d_in[7];
    const float* Wu = (const float*)d_in[8];
    const float* bu = (const float*)d_in[9];
    float* out = (float*)d_out;

    cudaFuncSetAttribute(vq_expert_kernel,
                         cudaFuncAttributeMaxDynamicSharedMemorySize, SMEM_BYTES);

    vq_precompute_kernel<<<289, 128>>>(cb, Wd, bd, Wp, bp, Wo, bo, Wu, bu);
    vq_expert_kernel<<<148, THREADS, SMEM_BYTES>>>(x, cb, bd, bp, out);
}

// round 17
// speedup vs baseline: 1.6884x; 1.3898x over previous
#include <cuda_runtime.h>
#include <cuda_bf16.h>
#include <cstdint>

// VQExpert round 17: BOTH GEMMs on mma.sync (bf16 double-split), z stays in
// registers (fold C-fragments feed scan A-fragments directly).
//   fold:  zC(16x32) = Xhi/lo(16x128) @ Mhi/lo^T   (mma, 3-term) + bz
//   scan:  S(16x256) = [zh zl zh](16x96) @ [ch ch cl]^T (mma, R16-validated)
//   guard: packed-key margin < TH or sign bit -> exact_row (R4 bit-exact, fp32)
//   y = clamp(T[idx])

typedef unsigned long long ull;
#define FULLMASK 0xffffffffu

constexpr int NROW   = 500000;
constexpr int WARPS  = 16;
constexpr int THREADS = WARPS * 32;              // 512
constexpr int RPW    = 16;
constexpr int TILE   = WARPS * RPW;              // 256
constexpr int NTILES = (NROW + TILE - 1) / TILE; // 1954
constexpr float BOFF = 64.0f;
constexpr float TH   = 1.2e-2f;

// smem layout (float units)
constexpr int O_CNB = 0;        // 256: 64 - cn/2
constexpr int O_CN  = 256;      // 256 code norms (exact path)
constexpr int O_BD  = 512;
constexpr int O_BP  = 640;
constexpr int O_BZ  = 672;
constexpr int O_B2F = 704;      // cb fragments (8192 uints)
constexpr int O_MBF = 8896;     // M fragments hi/lo (4096 uints)
constexpr int O_HS  = 12992;    // 16 warps x 160 exact scratch
constexpr int O_BC  = 15552;    // 16 warps x 16 idx
constexpr int SMEM_FLOATS = O_BC + WARPS * 16;   // 15808
constexpr int SMEM_BYTES  = SMEM_FLOATS * 4;     // 63,232 B

__device__ float g_T[256 * 128];
__device__ float g_M[32 * 128];
__device__ float g_bz[32];
__device__ __align__(16) float g_Wd2[128 * 128];  // exact path packs
__device__ __align__(16) float g_Wp2[32 * 128];
__device__ __align__(16) float g_cbq[256 * 32];
__device__ unsigned g_B2f[8192];                  // cb mma B-fragments
__device__ unsigned g_MBf[4096];                  // M mma B-fragments (hi|lo)

__device__ __forceinline__ ull ffma2(ull a, ull b, ull c) {
    ull d;
    asm("fma.rn.f32x2 %0, %1, %2, %3;" : "=l"(d) : "l"(a), "l"(b), "l"(c));
    return d;
}
__device__ __forceinline__ float f2sum(ull v) {
    float a, b;
    asm("mov.b64 {%0, %1}, %2;" : "=f"(a), "=f"(b) : "l"(v));
    return a + b;
}
__device__ __forceinline__ unsigned fkey(float s) {
    unsigned u = __float_as_uint(s);
    return u ^ ((u >> 31) ? 0xFFFFFFFFu : 0x80000000u);
}
__device__ __forceinline__ unsigned cvt_bf16x2(float a, float b) {
    unsigned r;
    asm("cvt.rn.bf16x2.f32 %0, %1, %2;" : "=r"(r) : "f"(b), "f"(a));
    return r;
}
__device__ __forceinline__ unsigned bf16bits(float f) {
    __nv_bfloat16 h = __float2bfloat16(f);
    return (unsigned)*(unsigned short*)&h;
}
__device__ __forceinline__ float rsub(float f) {
    return f - __bfloat162float(__float2bfloat16(f));
}
__device__ __forceinline__ void mma_bf16(float* c, const unsigned* a, unsigned b0, unsigned b1) {
    asm volatile("mma.sync.aligned.m16n8k16.row.col.f32.bf16.bf16.f32 "
                 "{%0,%1,%2,%3}, {%4,%5,%6,%7}, {%8,%9}, {%0,%1,%2,%3};"
                 : "+f"(c[0]), "+f"(c[1]), "+f"(c[2]), "+f"(c[3])
                 : "r"(a[0]), "r"(a[1]), "r"(a[2]), "r"(a[3]), "r"(b0), "r"(b1));
}

// ---------------- prologue ----------------
__global__ void __launch_bounds__(128)
vq_precompute_kernel(const float* __restrict__ cb,
                     const float* __restrict__ Wd, const float* __restrict__ bd,
                     const float* __restrict__ Wp, const float* __restrict__ bp,
                     const float* __restrict__ Wo, const float* __restrict__ bo,
                     const float* __restrict__ Wu, const float* __restrict__ bu)
{
    __shared__ float v[128];
    const int i = threadIdx.x;
    const int c = blockIdx.x;
    if (c < 256) {
        float s = 0.f;
        #pragma unroll 8
        for (int d = 0; d < 32; d++) s = fmaf(cb[c * 32 + d], Wo[i * 32 + d], s);
        v[i] = s;
        __syncthreads();
        float t = 0.f, Bi = bu[i];
        #pragma unroll 8
        for (int j = 0; j < 128; j++) {
            t  = fmaf(v[j],  Wu[i * 128 + j], t);
            Bi = fmaf(bo[j], Wu[i * 128 + j], Bi);
        }
        g_T[c * 128 + i] = t + Bi;

        const int t0 = c * 128 + i;
        if (t0 < 16384) {
            int j = t0 >> 7, k = t0 & 127;
            g_Wd2[(k >> 1) * 256 + j * 2 + (k & 1)] = Wd[t0];
        }
        if (t0 < 4096) {
            int cc = t0 >> 7, k = t0 & 127;
            g_Wp2[(k >> 2) * 128 + cc * 4 + (k & 3)] = Wp[t0];
        }
        if (t0 < 8192) {
            int cc = t0 >> 5, d = t0 & 31;
            g_cbq[(d >> 2) * 1024 + cc * 4 + (d & 3)] = cb[t0];
        }
        if (t0 < 8192) {            // cb mma B-fragments (R16-validated mapping)
            unsigned u = (unsigned)t0;
            int kt = u >> 11, rem = u & 2047;
            int nt = rem >> 6, rem2 = rem & 63;
            int l = rem2 >> 1, r = rem2 & 1;
            int n = nt * 8 + (l >> 2);
            int kin = 2 * (l & 3) + r * 8;
            int d = (kt & 1) * 16 + kin;
            float f0 = cb[n * 32 + d], f1 = cb[n * 32 + d + 1];
            unsigned v0, v1;
            if (kt < 2) { v0 = bf16bits(f0); v1 = bf16bits(f1); }
            else        { v0 = bf16bits(rsub(f0)); v1 = bf16bits(rsub(f1)); }
            g_B2f[u] = v0 | (v1 << 16);
        }
    } else if (c < 288) {
        int zc = c - 256;
        double s = 0.0;
        for (int h = 0; h < 128; h++)
            s += (double)Wp[zc * 128 + h] * (double)Wd[h * 128 + i];
        g_M[zc * 128 + i] = (float)s;
    } else if (c == 288) {
        if (i < 32) {
            double s = (double)bp[i];
            for (int h = 0; h < 128; h++) s += (double)Wp[i * 128 + h] * (double)bd[h];
            g_bz[i] = (float)s;
        }
    } else {
        // M mma B-fragments: idx in [0, 4096): [kind2][kt8][nt4][l32][r2]
        int idx = (c - 289) * 128 + i;
        int kind = idx >> 11;
        int u2 = idx & 2047;
        int kt = u2 >> 8;
        int rem = u2 & 255;
        int nt = rem >> 6, rem2 = rem & 63;
        int l = rem2 >> 1, r = rem2 & 1;
        int n = nt * 8 + (l >> 2);
        int k = 16 * kt + 2 * (l & 3) + 8 * r;
        double m0 = 0.0, m1 = 0.0;
        for (int h = 0; h < 128; h++) {
            double wp = (double)Wp[n * 128 + h];
            m0 += wp * (double)Wd[h * 128 + k];
            m1 += wp * (double)Wd[h * 128 + k + 1];
        }
        float f0 = (float)m0, f1 = (float)m1;
        unsigned v0, v1;
        if (kind == 0) { v0 = bf16bits(f0); v1 = bf16bits(f1); }
        else           { v0 = bf16bits(rsub(f0)); v1 = bf16bits(rsub(f1)); }
        g_MBf[idx] = v0 | (v1 << 16);
    }
}

// exact two-step recompute (R4 bit-exact order); weights from GLOBAL packs.
__device__ __noinline__ int exact_row_g(const float* __restrict__ xrow,
                                        const float* __restrict__ cnsm,
                                        float* hs, float* zrow, int lane,
                                        float2 bd0, float2 bd1, float bpv)
{
    ull a0 = 0, a1 = 0, a2 = 0, a3 = 0;
    for (int pp = 0; pp < 32; pp++) {
        const float* b0 = g_Wd2 + (2 * pp) * 256;
        const float* b1 = b0 + 256;
        ulonglong2 wa0 = *(const ulonglong2*)(b0 + 4 * lane);
        ulonglong2 wb0 = *(const ulonglong2*)(b0 + 128 + 4 * lane);
        ulonglong2 wa1 = *(const ulonglong2*)(b1 + 4 * lane);
        ulonglong2 wb1 = *(const ulonglong2*)(b1 + 128 + 4 * lane);
        ulonglong2 xv  = *(const ulonglong2*)(xrow + 4 * pp);
        a0 = ffma2(xv.x, wa0.x, a0); a1 = ffma2(xv.x, wa0.y, a1);
        a2 = ffma2(xv.x, wb0.x, a2); a3 = ffma2(xv.x, wb0.y, a3);
        a0 = ffma2(xv.y, wa1.x, a0); a1 = ffma2(xv.y, wa1.y, a1);
        a2 = ffma2(xv.y, wb1.x, a2); a3 = ffma2(xv.y, wb1.y, a3);
    }
    __syncwarp();
    hs[2 * lane]          = bd0.x + f2sum(a0);
    hs[2 * lane + 1]      = bd0.y + f2sum(a1);
    hs[64 + 2 * lane]     = bd1.x + f2sum(a2);
    hs[64 + 2 * lane + 1] = bd1.y + f2sum(a3);
    __syncwarp();
    ull zacc = 0;
    for (int kq = 0; kq < 32; kq++) {
        ulonglong2 w  = *(const ulonglong2*)(g_Wp2 + kq * 128 + 4 * lane);
        ulonglong2 h2 = *(const ulonglong2*)(hs + 4 * kq);
        zacc = ffma2(h2.x, w.x, zacc);
        zacc = ffma2(h2.y, w.y, zacc);
    }
    __syncwarp();
    zrow[lane] = bpv + f2sum(zacc);
    __syncwarp();
    ull dd[8];
    #pragma unroll
    for (int g = 0; g < 8; g++) dd[g] = 0ull;
    for (int dq = 0; dq < 8; dq++) {
        ulonglong2 zq = *(const ulonglong2*)(zrow + 4 * dq);
        #pragma unroll
        for (int g = 0; g < 8; g++) {
            ulonglong2 c2 = *(const ulonglong2*)(g_cbq + dq * 1024 + (g * 32 + lane) * 4);
            dd[g] = ffma2(zq.x, c2.x, dd[g]);
            dd[g] = ffma2(zq.y, c2.y, dd[g]);
        }
    }
    unsigned bk = 0xFFFFFFFFu, bi = 0;
    #pragma unroll
    for (int g = 0; g < 8; g++) {
        float s = cnsm[g * 32 + lane] - 2.0f * f2sum(dd[g]);
        unsigned k = fkey(s);
        if (k < bk) { bk = k; bi = (unsigned)((g << 5) | lane); }
    }
    unsigned m = __reduce_min_sync(FULLMASK, bk);
    unsigned cand = (bk == m) ? bi : 0xFFFFFFFFu;
    return (int)__reduce_min_sync(FULLMASK, cand);
}

// ---------------- main kernel ----------------
__global__ void __launch_bounds__(THREADS, 1)
vq_expert_kernel(const float* __restrict__ x,
                 const float* __restrict__ cb,
                 const float* __restrict__ bd, const float* __restrict__ bp,
                 float* __restrict__ out)
{
    extern __shared__ float sm[];
    const int tid  = threadIdx.x;
    const int wid  = tid >> 5;
    const int lane = tid & 31;

    // stage static smem
    for (int i = tid; i < 8192; i += THREADS)
        ((unsigned*)(sm + O_B2F))[i] = g_B2f[i];
    for (int i = tid; i < 4096; i += THREADS)
        ((unsigned*)(sm + O_MBF))[i] = g_MBf[i];
    for (int c = tid; c < 256; c += THREADS) {
        float s = 0.f;
        #pragma unroll 8
        for (int d = 0; d < 32; d++) { float v = cb[c * 32 + d]; s = fmaf(v, v, s); }
        sm[O_CN + c]  = s;
        sm[O_CNB + c] = BOFF - 0.5f * s;
    }
    if (tid < 128) sm[O_BD + tid] = bd[tid];
    else if (tid < 160) sm[O_BP + tid - 128] = bp[tid - 128];
    else if (tid < 192) sm[O_BZ + tid - 160] = g_bz[tid - 160];
    if (blockIdx.x == 0 && tid == 0)
        out[(size_t)NROW * 128 + NROW] = 0.0f;    // commit_loss == 0 exactly
    __syncthreads();

    float* myhs = sm + O_HS + wid * 160;
    float* myzr = myhs + 128;
    int*   bcw  = (int*)(sm + O_BC) + wid * 16;

    const float2 bd0 = *(const float2*)(sm + O_BD + 2 * lane);
    const float2 bd1 = *(const float2*)(sm + O_BD + 64 + 2 * lane);
    const float  bpv = sm[O_BP + lane];

    const int g  = lane >> 2;
    const int tg = lane & 3;

    const uint2* Bf   = (const uint2*)(sm + O_B2F);
    const uint2* MBf2 = (const uint2*)(sm + O_MBF);

    float* outY = out;
    float* outI = out + (size_t)NROW * 128;

    for (int tile = blockIdx.x; tile < NTILES; tile += gridDim.x) {
        const int row0 = tile * TILE + wid * RPW;
        if (row0 >= NROW) continue;
        const bool okg = (row0 + g)     < NROW;
        const bool okh = (row0 + g + 8) < NROW;
        const float* xr0 = x + (size_t)(row0 + g) * 128;
        const float* xr1 = x + (size_t)(row0 + g + 8) * 128;

        // ---- fold via mma: zC(16x32) = X @ M^T (double-bf16, 3 terms) ----
        float C[4][4];
        #pragma unroll
        for (int nt = 0; nt < 4; nt++)
            #pragma unroll
            for (int j = 0; j < 4; j++) C[nt][j] = 0.f;

        #pragma unroll
        for (int kt = 0; kt < 8; kt++) {
            const int c0 = kt * 16 + 2 * tg;
            float2 zz = make_float2(0.f, 0.f);
            float2 p00 = okg ? *(const float2*)(xr0 + c0)     : zz;
            float2 p10 = okh ? *(const float2*)(xr1 + c0)     : zz;
            float2 p01 = okg ? *(const float2*)(xr0 + c0 + 8) : zz;
            float2 p11 = okh ? *(const float2*)(xr1 + c0 + 8) : zz;
            unsigned Ah[4], Al[4];
            Ah[0] = cvt_bf16x2(p00.x, p00.y);
            Ah[1] = cvt_bf16x2(p10.x, p10.y);
            Ah[2] = cvt_bf16x2(p01.x, p01.y);
            Ah[3] = cvt_bf16x2(p11.x, p11.y);
            Al[0] = cvt_bf16x2(rsub(p00.x), rsub(p00.y));
            Al[1] = cvt_bf16x2(rsub(p10.x), rsub(p10.y));
            Al[2] = cvt_bf16x2(rsub(p01.x), rsub(p01.y));
            Al[3] = cvt_bf16x2(rsub(p11.x), rsub(p11.y));
            #pragma unroll
            for (int nt = 0; nt < 4; nt++) {
                uint2 bh = MBf2[(kt * 4 + nt) * 32 + lane];
                uint2 bl = MBf2[((8 + kt) * 4 + nt) * 32 + lane];
                mma_bf16(C[nt], Ah, bh.x, bh.y);
                mma_bf16(C[nt], Al, bh.x, bh.y);
                mma_bf16(C[nt], Ah, bl.x, bl.y);
            }
        }
        #pragma unroll
        for (int nt = 0; nt < 4; nt++) {
            float2 b2 = *(const float2*)(sm + O_BZ + nt * 8 + 2 * tg);
            C[nt][0] += b2.x; C[nt][1] += b2.y;
            C[nt][2] += b2.x; C[nt][3] += b2.y;
        }

        // ---- build scan A fragments directly from fold C fragments ----
        unsigned A6[4][4];
        A6[0][0] = cvt_bf16x2(C[0][0], C[0][1]);
        A6[0][1] = cvt_bf16x2(C[0][2], C[0][3]);
        A6[0][2] = cvt_bf16x2(C[1][0], C[1][1]);
        A6[0][3] = cvt_bf16x2(C[1][2], C[1][3]);
        A6[1][0] = cvt_bf16x2(C[2][0], C[2][1]);
        A6[1][1] = cvt_bf16x2(C[2][2], C[2][3]);
        A6[1][2] = cvt_bf16x2(C[3][0], C[3][1]);
        A6[1][3] = cvt_bf16x2(C[3][2], C[3][3]);
        A6[2][0] = cvt_bf16x2(rsub(C[0][0]), rsub(C[0][1]));
        A6[2][1] = cvt_bf16x2(rsub(C[0][2]), rsub(C[0][3]));
        A6[2][2] = cvt_bf16x2(rsub(C[1][0]), rsub(C[1][1]));
        A6[2][3] = cvt_bf16x2(rsub(C[1][2]), rsub(C[1][3]));
        A6[3][0] = cvt_bf16x2(rsub(C[2][0]), rsub(C[2][1]));
        A6[3][1] = cvt_bf16x2(rsub(C[2][2]), rsub(C[2][3]));
        A6[3][2] = cvt_bf16x2(rsub(C[3][0]), rsub(C[3][1]));
        A6[3][3] = cvt_bf16x2(rsub(C[3][2]), rsub(C[3][3]));

        // ---- MMA scan: 32 ntiles (pairs), 6 K-steps each (R16-validated) ----
        unsigned Bg = 0u, Sg = 0u, Bh = 0u, Sh = 0u;
        const int AI[6] = {0, 1, 2, 3, 0, 1};
        const int KB[6] = {0, 1, 0, 1, 2, 3};

        #pragma unroll 2
        for (int ntp = 0; ntp < 16; ntp++) {
            int nt0 = 2 * ntp, nt1 = nt0 + 1;
            float C0[4] = {0.f, 0.f, 0.f, 0.f};
            float C1[4] = {0.f, 0.f, 0.f, 0.f};
            #pragma unroll
            for (int s = 0; s < 6; s++) {
                uint2 b0 = Bf[(KB[s] * 32 + nt0) * 32 + lane];
                mma_bf16(C0, A6[AI[s]], b0.x, b0.y);
                uint2 b1 = Bf[(KB[s] * 32 + nt1) * 32 + lane];
                mma_bf16(C1, A6[AI[s]], b1.x, b1.y);
            }
            #pragma unroll
            for (int q = 0; q < 2; q++) {
                const float* Cc = q ? C1 : C0;
                int nt = q ? nt1 : nt0;
                float2 cnb = *(const float2*)(sm + O_CNB + nt * 8 + 2 * tg);
                int col0 = nt * 8 + 2 * tg;
                float sc; unsigned pk, nb;
                sc = Cc[0] + cnb.x;
                pk = (__float_as_uint(sc) & 0xFFFFFF00u) | ((unsigned)col0 ^ 0xFFu);
                nb = umax(Bg, pk); Sg = umax(Sg, umin(Bg, pk)); Bg = nb;
                sc = Cc[1] + cnb.y;
                pk = (__float_as_uint(sc) & 0xFFFFFF00u) | ((unsigned)(col0 + 1) ^ 0xFFu);
                nb = umax(Bg, pk); Sg = umax(Sg, umin(Bg, pk)); Bg = nb;
                sc = Cc[2] + cnb.x;
                pk = (__float_as_uint(sc) & 0xFFFFFF00u) | ((unsigned)col0 ^ 0xFFu);
                nb = umax(Bh, pk); Sh = umax(Sh, umin(Bh, pk)); Bh = nb;
                sc = Cc[3] + cnb.y;
                pk = (__float_as_uint(sc) & 0xFFFFFF00u) | ((unsigned)(col0 + 1) ^ 0xFFu);
                nb = umax(Bh, pk); Sh = umax(Sh, umin(Bh, pk)); Bh = nb;
            }
        }

        // ---- quad reduce (4 lanes per row) ----
        #pragma unroll
        for (int off = 1; off <= 2; off <<= 1) {
            unsigned ob = __shfl_xor_sync(FULLMASK, Bg, off);
            unsigned os = __shfl_xor_sync(FULLMASK, Sg, off);
            Sg = umax(umax(Sg, os), umin(Bg, ob)); Bg = umax(Bg, ob);
            ob = __shfl_xor_sync(FULLMASK, Bh, off);
            os = __shfl_xor_sync(FULLMASK, Sh, off);
            Sh = umax(umax(Sh, os), umin(Bh, ob)); Bh = umax(Bh, ob);
        }
        if (tg == 0) {
            unsigned Bs[2] = {Bg, Bh}, Ss[2] = {Sg, Sh};
            #pragma unroll
            for (int h = 0; h < 2; h++) {
                int r = g + h * 8;
                int res = 0;
                if (row0 + r < NROW) {
                    unsigned B = Bs[h], S = Ss[h];
                    float margin = __uint_as_float(B & 0xFFFFFF00u)
                                 - __uint_as_float(S & 0xFFFFFF00u);
                    res = (((int)B < 0) || !(margin >= TH))
                        ? -1 : (int)((B & 0xFFu) ^ 0xFFu);
                }
                bcw[r] = res;
            }
        }
        __syncwarp();

        // ---- fallback + epilogue ----
        #pragma unroll 4
        for (int r = 0; r < RPW; r++) {
            int grow = row0 + r;
            if (grow >= NROW) continue;
            int idx = bcw[r];
            if (idx < 0)
                idx = exact_row_g(x + (size_t)grow * 128, sm + O_CN,
                                  myhs, myzr, lane, bd0, bd1, bpv);
            float4 t = ((const float4*)(g_T + idx * 128))[lane];
            float4 y;
            y.x = fminf(fmaxf(t.x, -1.0f), 1.0f);
            y.y = fminf(fmaxf(t.y, -1.0f), 1.0f);
            y.z = fminf(fmaxf(t.z, -1.0f), 1.0f);
            y.w = fminf(fmaxf(t.w, -1.0f), 1.0f);
            ((float4*)(outY + (size_t)grow * 128))[lane] = y;
            if (lane == 0) outI[grow] = (float)idx;
        }
        __syncwarp();
    }
}

extern "C" void kernel_launch(void* const* d_in, const int* in_sizes, int n_in,
                              void* d_out, int out_size)
{
    const float* x  = (const float*)d_in[0];
    const float* Wd = (const float*)d_in[1];
    const float* bd = (const float*)d_in[2];
    const float* Wp = (const float*)d_in[3];
    const float* bp = (const float*)d_in[4];
    const float* cb = (const float*)d_in[5];
    const float* Wo = (const float*)d_in[6];
    const float* bo = (const float*)d_in[7];
    const float* Wu = (const float*)d_in[8];
    const float* bu = (const float*)d_in[9];
    float* out = (float*)d_out;

    cudaFuncSetAttribute(vq_expert_kernel,
                         cudaFuncAttributeMaxDynamicSharedMemorySize, SMEM_BYTES);

    vq_precompute_kernel<<<321, 128>>>(cb, Wd, bd, Wp, bp, Wo, bo, Wu, bu);
    vq_expert_kernel<<<148, THREADS, SMEM_BYTES>>>(x, cb, bd, bp, out);
}